// round 2
// baseline (speedup 1.0000x reference)
#include <cuda_runtime.h>
#include <math.h>

// Problem constants
#define TT 512
#define NB 64
#define DD 1024
#define HH 1024
#define TH 3072   // 3*H

// Scratch for gi = x @ w_ih^T + b_ih : [T*N, 3H] fp32 = 402 MB
__device__ float g_gi[TT * NB * TH];

// ---------------------------------------------------------------------------
// Kernel 1: gi GEMM.  C[M=32768, N=3072] = A[M,1024] @ B[3072,1024]^T + bias
// Classic 128x128x16 tiling, 256 threads, 8x8 per thread (4+4 split frags).
// ---------------------------------------------------------------------------
__global__ __launch_bounds__(256) void gi_gemm_kernel(
    const float* __restrict__ A,     // x  [32768, 1024]
    const float* __restrict__ B,     // w_ih [3072, 1024]
    const float* __restrict__ bias,  // b_ih [3072]
    float* __restrict__ C)           // gi [32768, 3072]
{
    __shared__ float As[16][132];
    __shared__ float Bs[16][132];

    const int tid = threadIdx.x;
    const int m0 = blockIdx.y * 128;
    const int n0 = blockIdx.x * 128;
    const int tx = tid & 15;   // col group
    const int ty = tid >> 4;   // row group
    const int lRow = tid >> 2;        // 0..63
    const int lK   = (tid & 3) * 4;   // 0,4,8,12

    float acc[8][8];
#pragma unroll
    for (int i = 0; i < 8; i++)
#pragma unroll
        for (int j = 0; j < 8; j++) acc[i][j] = 0.f;

    for (int k0 = 0; k0 < DD; k0 += 16) {
#pragma unroll
        for (int r = 0; r < 2; r++) {
            int mm = lRow + r * 64;
            float4 va = *(const float4*)&A[(size_t)(m0 + mm) * DD + k0 + lK];
            As[lK + 0][mm] = va.x; As[lK + 1][mm] = va.y;
            As[lK + 2][mm] = va.z; As[lK + 3][mm] = va.w;
            float4 vb = *(const float4*)&B[(size_t)(n0 + mm) * DD + k0 + lK];
            Bs[lK + 0][mm] = vb.x; Bs[lK + 1][mm] = vb.y;
            Bs[lK + 2][mm] = vb.z; Bs[lK + 3][mm] = vb.w;
        }
        __syncthreads();
#pragma unroll
        for (int k = 0; k < 16; k++) {
            float a[8], b[8];
            *(float4*)&a[0] = *(float4*)&As[k][ty * 4];
            *(float4*)&a[4] = *(float4*)&As[k][64 + ty * 4];
            *(float4*)&b[0] = *(float4*)&Bs[k][tx * 4];
            *(float4*)&b[4] = *(float4*)&Bs[k][64 + tx * 4];
#pragma unroll
            for (int i = 0; i < 8; i++)
#pragma unroll
                for (int j = 0; j < 8; j++)
                    acc[i][j] += a[i] * b[j];
        }
        __syncthreads();
    }

#pragma unroll
    for (int i = 0; i < 8; i++) {
        int m = m0 + ((i < 4) ? (ty * 4 + i) : (64 + ty * 4 + i - 4));
#pragma unroll
        for (int j = 0; j < 8; j++) {
            int n = n0 + ((j < 4) ? (tx * 4 + j) : (64 + tx * 4 + j - 4));
            C[(size_t)m * TH + n] = acc[i][j] + bias[n];
        }
    }
}

// ---------------------------------------------------------------------------
// Kernel 2: one GRU step.
// grid = (64 j-tiles of 16, 2 n-halves of 32), block = 192 threads.
// Block computes gh tile [32 n x 48 cols] (48 = 3 gates x 16 j) as a GEMM
// over K=1024 with 2-way K-split across thread groups, then fuses gates.
// h_prev is read from the previous step's output slice.
// ---------------------------------------------------------------------------
__device__ __forceinline__ float sigmoidf_(float x) {
    return 1.f / (1.f + expf(-x));
}

__global__ __launch_bounds__(192) void gru_step_kernel(
    const float* __restrict__ gi_t,   // [64, 3072]
    const float* __restrict__ mask_t, // [64]
    const float* __restrict__ w_hh,   // [3072, 1024]
    const float* __restrict__ b_hh,   // [3072]
    const float* __restrict__ h_prev, // [64, 1024]
    float* __restrict__ h_out)        // [64, 1024]
{
    __shared__ float Hs[2][16][36];   // [kgroup][k][n]  (n-padded)
    __shared__ float Ws[2][16][52];   // [kgroup][k][col]
    __shared__ float gh_s[48][33];    // [col][n]
    __shared__ float red[96][16];     // cross-kgroup reduction
    __shared__ float msk[32];

    const int tid = threadIdx.x;
    const int kg  = tid / 96;         // 0/1 : K-half
    const int t   = tid % 96;
    const int trow = t / 12;          // 0..7  -> 4 n each
    const int tcol = t % 12;          // 0..11 -> 4 cols each
    const int j0 = blockIdx.x * 16;
    const int n_base = blockIdx.y * 32;
    const int kbase0 = kg * 512;

    if (tid < 32) msk[tid] = mask_t[n_base + tid];

    float acc[4][4];
#pragma unroll
    for (int r = 0; r < 4; r++)
#pragma unroll
        for (int c = 0; c < 4; c++) acc[r][c] = 0.f;

    __syncthreads();   // msk ready

    for (int kc = 0; kc < 512; kc += 16) {
        const int kb = kbase0 + kc;

        // load H tile: 32n x 16k = 128 float4 slots over 96 threads
        {
            int s = t;
#pragma unroll
            for (int rep = 0; rep < 2; rep++, s += 96) {
                if (s < 128) {
                    int n  = s >> 2;
                    int kq = (s & 3) * 4;
                    float4 hv = *(const float4*)&h_prev[(n_base + n) * HH + kb + kq];
                    float m = msk[n];
                    Hs[kg][kq + 0][n] = hv.x * m;
                    Hs[kg][kq + 1][n] = hv.y * m;
                    Hs[kg][kq + 2][n] = hv.z * m;
                    Hs[kg][kq + 3][n] = hv.w * m;
                }
            }
        }
        // load W tile: 48 cols x 16k = 192 float4 slots over 96 threads
        {
            int s = t;
#pragma unroll
            for (int rep = 0; rep < 2; rep++, s += 96) {
                int col = s >> 2;
                int kq  = (s & 3) * 4;
                int g = col >> 4, jj = col & 15;
                int row = g * HH + j0 + jj;
                float4 wv = *(const float4*)&w_hh[(size_t)row * HH + kb + kq];
                Ws[kg][kq + 0][col] = wv.x;
                Ws[kg][kq + 1][col] = wv.y;
                Ws[kg][kq + 2][col] = wv.z;
                Ws[kg][kq + 3][col] = wv.w;
            }
        }
        __syncthreads();
#pragma unroll
        for (int k = 0; k < 16; k++) {
            float hr[4], wc[4];
            *(float4*)hr = *(const float4*)&Hs[kg][k][trow * 4];
            *(float4*)wc = *(const float4*)&Ws[kg][k][tcol * 4];
#pragma unroll
            for (int r = 0; r < 4; r++)
#pragma unroll
                for (int c = 0; c < 4; c++)
                    acc[r][c] += hr[r] * wc[c];
        }
        __syncthreads();
    }

    // reduce across the two K-halves
    if (kg == 1) {
#pragma unroll
        for (int r = 0; r < 4; r++)
#pragma unroll
            for (int c = 0; c < 4; c++)
                red[t][r * 4 + c] = acc[r][c];
    }
    __syncthreads();
    if (kg == 0) {
#pragma unroll
        for (int r = 0; r < 4; r++) {
            int n = trow * 4 + r;
#pragma unroll
            for (int c = 0; c < 4; c++) {
                int col = tcol * 4 + c;
                int g = col >> 4, jj = col & 15;
                gh_s[col][n] = acc[r][c] + red[t][r * 4 + c] + b_hh[g * HH + j0 + jj];
            }
        }
    }
    __syncthreads();

    // fuse gates: 32n x 16j outputs over 192 threads
    for (int idx = tid; idx < 512; idx += 192) {
        int jj = idx & 15;
        int n  = idx >> 4;
        int nglob = n_base + n;
        int j = j0 + jj;
        float ghr = gh_s[jj][n];
        float ghz = gh_s[16 + jj][n];
        float ghn = gh_s[32 + jj][n];
        const float* girow = gi_t + (size_t)nglob * TH;
        float gir = girow[j];
        float giz = girow[HH + j];
        float gin = girow[2 * HH + j];
        float hm = h_prev[nglob * HH + j] * msk[n];
        float r = sigmoidf_(gir + ghr);
        float z = sigmoidf_(giz + ghz);
        float nn = tanhf(gin + r * ghn);
        h_out[nglob * HH + j] = (1.f - z) * nn + z * hm;
    }
}

// ---------------------------------------------------------------------------
extern "C" void kernel_launch(void* const* d_in, const int* in_sizes, int n_in,
                              void* d_out, int out_size)
{
    const float* x    = (const float*)d_in[0];
    const float* hx   = (const float*)d_in[1];
    const float* mask = (const float*)d_in[2];
    const float* w_ih = (const float*)d_in[3];
    const float* w_hh = (const float*)d_in[4];
    const float* b_ih = (const float*)d_in[5];
    const float* b_hh = (const float*)d_in[6];
    float* out = (float*)d_out;

    float* gi = nullptr;
    cudaGetSymbolAddress((void**)&gi, g_gi);

    // Phase 1: bulk input projection
    dim3 gg(TH / 128, (TT * NB) / 128);   // (24, 256)
    gi_gemm_kernel<<<gg, 256>>>(x, w_ih, b_ih, gi);

    // Phase 2: sequential scan, one launch per timestep
    dim3 sg(HH / 16, 2);                  // (64, 2) = 128 blocks
    for (int tm = 0; tm < TT; tm++) {
        const float* hp = (tm == 0) ? hx : (out + (size_t)(tm - 1) * NB * HH);
        gru_step_kernel<<<sg, 192>>>(gi + (size_t)tm * NB * TH,
                                     mask + tm * NB,
                                     w_hh, b_hh,
                                     hp,
                                     out + (size_t)tm * NB * HH);
    }

    // h_final == out[T-1]
    cudaMemcpyAsync(out + (size_t)TT * NB * HH,
                    out + (size_t)(TT - 1) * NB * HH,
                    (size_t)NB * HH * sizeof(float),
                    cudaMemcpyDeviceToDevice, 0);
}

// round 3
// speedup vs baseline: 1.1914x; 1.1914x over previous
#include <cuda_runtime.h>
#include <math.h>

// Problem constants
#define TT 512
#define NB 64
#define DD 1024
#define HH 1024
#define TH 3072   // 3*H

// Scratch for gi = x @ w_ih^T + b_ih : [T*N, 3H] fp32 = 402 MB
__device__ float g_gi[TT * NB * TH];

// ---------------------------------------------------------------------------
// Kernel 1: gi GEMM.  C[M=32768, N=3072] = A[M,1024] @ B[3072,1024]^T + bias
// ---------------------------------------------------------------------------
__global__ __launch_bounds__(256) void gi_gemm_kernel(
    const float* __restrict__ A,     // x  [32768, 1024]
    const float* __restrict__ B,     // w_ih [3072, 1024]
    const float* __restrict__ bias,  // b_ih [3072]
    float* __restrict__ C)           // gi [32768, 3072]
{
    __shared__ float As[16][132];
    __shared__ float Bs[16][132];

    const int tid = threadIdx.x;
    const int m0 = blockIdx.y * 128;
    const int n0 = blockIdx.x * 128;
    const int tx = tid & 15;
    const int ty = tid >> 4;
    const int lRow = tid >> 2;
    const int lK   = (tid & 3) * 4;

    float acc[8][8];
#pragma unroll
    for (int i = 0; i < 8; i++)
#pragma unroll
        for (int j = 0; j < 8; j++) acc[i][j] = 0.f;

    for (int k0 = 0; k0 < DD; k0 += 16) {
#pragma unroll
        for (int r = 0; r < 2; r++) {
            int mm = lRow + r * 64;
            float4 va = *(const float4*)&A[(size_t)(m0 + mm) * DD + k0 + lK];
            As[lK + 0][mm] = va.x; As[lK + 1][mm] = va.y;
            As[lK + 2][mm] = va.z; As[lK + 3][mm] = va.w;
            float4 vb = *(const float4*)&B[(size_t)(n0 + mm) * DD + k0 + lK];
            Bs[lK + 0][mm] = vb.x; Bs[lK + 1][mm] = vb.y;
            Bs[lK + 2][mm] = vb.z; Bs[lK + 3][mm] = vb.w;
        }
        __syncthreads();
#pragma unroll
        for (int k = 0; k < 16; k++) {
            float a[8], b[8];
            *(float4*)&a[0] = *(float4*)&As[k][ty * 4];
            *(float4*)&a[4] = *(float4*)&As[k][64 + ty * 4];
            *(float4*)&b[0] = *(float4*)&Bs[k][tx * 4];
            *(float4*)&b[4] = *(float4*)&Bs[k][64 + tx * 4];
#pragma unroll
            for (int i = 0; i < 8; i++)
#pragma unroll
                for (int j = 0; j < 8; j++)
                    acc[i][j] += a[i] * b[j];
        }
        __syncthreads();
    }

#pragma unroll
    for (int i = 0; i < 8; i++) {
        int m = m0 + ((i < 4) ? (ty * 4 + i) : (64 + ty * 4 + i - 4));
#pragma unroll
        for (int j = 0; j < 8; j++) {
            int n = n0 + ((j < 4) ? (tx * 4 + j) : (64 + tx * 4 + j - 4));
            C[(size_t)m * TH + n] = acc[i][j] + bias[n];
        }
    }
}

// ---------------------------------------------------------------------------
// Kernel 2: one GRU step — occupancy-focused redesign.
// grid = (64 j-tiles of 16, 2 n-halves of 32), block = 256 threads
//       = 2 K-groups (K=512 each) x 128 threads.
// Thread tile: 4 n x 1 j x 3 gates (12 accumulators) -> thread-local gate
// fusion, no gh smem round-trip. One cross-kgroup reduction at the end.
// ---------------------------------------------------------------------------
__device__ __forceinline__ float sigmoidf_(float x) {
    return 1.f / (1.f + expf(-x));
}

__global__ __launch_bounds__(256) void gru_step_kernel(
    const float* __restrict__ gi_t,   // [64, 3072]
    const float* __restrict__ mask_t, // [64]
    const float* __restrict__ w_hh,   // [3072, 1024]
    const float* __restrict__ b_hh,   // [3072]
    const float* __restrict__ h_prev, // [64, 1024]
    float* __restrict__ h_out)        // [64, 1024]
{
    __shared__ __align__(16) float Hs[2][32][36];  // [kg][k][n] (36: float4-aligned rows)
    __shared__ float Ws[2][32][49];                // [kg][k][col] col = g*16+jj
    __shared__ float red[128][13];                 // kg1 partials
    __shared__ float msk[32];

    const int tid = threadIdx.x;
    const int kg  = tid >> 7;        // 0/1 K-half
    const int t   = tid & 127;
    const int tn  = t >> 4;          // 0..7 -> 4 n each
    const int tj  = t & 15;          // j within tile
    const int j0  = blockIdx.x * 16;
    const int n_base = blockIdx.y * 32;
    const int kbase0 = kg * 512;

    if (tid < 32) msk[tid] = mask_t[n_base + tid];

    float accr[4], accz[4], accn[4];
#pragma unroll
    for (int i = 0; i < 4; i++) { accr[i] = 0.f; accz[i] = 0.f; accn[i] = 0.f; }

    __syncthreads();   // msk ready

    for (int kc = 0; kc < 512; kc += 32) {
        const int kb = kbase0 + kc;

        // load H tile: 32n x 32k per kgroup = 256 float4 over 128 threads (2 each)
#pragma unroll
        for (int rep = 0; rep < 2; rep++) {
            int s  = t + rep * 128;
            int n  = s >> 3;            // 0..31
            int kq = (s & 7) * 4;       // 0,4,...,28
            float4 hv = *(const float4*)&h_prev[(n_base + n) * HH + kb + kq];
            float m = msk[n];
            Hs[kg][kq + 0][n] = hv.x * m;
            Hs[kg][kq + 1][n] = hv.y * m;
            Hs[kg][kq + 2][n] = hv.z * m;
            Hs[kg][kq + 3][n] = hv.w * m;
        }
        // load W tile: 48 cols x 32k = 384 float4 over 128 threads (3 each)
#pragma unroll
        for (int rep = 0; rep < 3; rep++) {
            int s   = t + rep * 128;
            int col = s >> 3;           // 0..47
            int kq  = (s & 7) * 4;
            int g = col >> 4, jj = col & 15;
            float4 wv = *(const float4*)&w_hh[(size_t)(g * HH + j0 + jj) * HH + kb + kq];
            Ws[kg][kq + 0][col] = wv.x;
            Ws[kg][kq + 1][col] = wv.y;
            Ws[kg][kq + 2][col] = wv.z;
            Ws[kg][kq + 3][col] = wv.w;
        }
        __syncthreads();

#pragma unroll
        for (int k = 0; k < 32; k++) {
            float4 hv = *(const float4*)&Hs[kg][k][tn * 4];
            float wr = Ws[kg][k][tj];
            float wz = Ws[kg][k][16 + tj];
            float wn = Ws[kg][k][32 + tj];
            accr[0] += hv.x * wr; accr[1] += hv.y * wr;
            accr[2] += hv.z * wr; accr[3] += hv.w * wr;
            accz[0] += hv.x * wz; accz[1] += hv.y * wz;
            accz[2] += hv.z * wz; accz[3] += hv.w * wz;
            accn[0] += hv.x * wn; accn[1] += hv.y * wn;
            accn[2] += hv.z * wn; accn[3] += hv.w * wn;
        }
        __syncthreads();
    }

    // cross-kgroup reduction
    if (kg == 1) {
#pragma unroll
        for (int i = 0; i < 4; i++) {
            red[t][i]     = accr[i];
            red[t][4 + i] = accz[i];
            red[t][8 + i] = accn[i];
        }
    }
    __syncthreads();

    if (kg == 0) {
        const int j = j0 + tj;
        const float br = b_hh[j];
        const float bz = b_hh[HH + j];
        const float bn = b_hh[2 * HH + j];
#pragma unroll
        for (int i = 0; i < 4; i++) {
            int nl = tn * 4 + i;
            int nglob = n_base + nl;
            float ghr = accr[i] + red[t][i]     + br;
            float ghz = accz[i] + red[t][4 + i] + bz;
            float ghn = accn[i] + red[t][8 + i] + bn;
            const float* girow = gi_t + (size_t)nglob * TH;
            float gir = girow[j];
            float giz = girow[HH + j];
            float gin = girow[2 * HH + j];
            float hm  = h_prev[nglob * HH + j] * msk[nl];
            float r  = sigmoidf_(gir + ghr);
            float z  = sigmoidf_(giz + ghz);
            float nn = tanhf(gin + r * ghn);
            h_out[nglob * HH + j] = (1.f - z) * nn + z * hm;
        }
    }
}

// ---------------------------------------------------------------------------
extern "C" void kernel_launch(void* const* d_in, const int* in_sizes, int n_in,
                              void* d_out, int out_size)
{
    const float* x    = (const float*)d_in[0];
    const float* hx   = (const float*)d_in[1];
    const float* mask = (const float*)d_in[2];
    const float* w_ih = (const float*)d_in[3];
    const float* w_hh = (const float*)d_in[4];
    const float* b_ih = (const float*)d_in[5];
    const float* b_hh = (const float*)d_in[6];
    float* out = (float*)d_out;

    float* gi = nullptr;
    cudaGetSymbolAddress((void**)&gi, g_gi);

    // Phase 1: bulk input projection
    dim3 gg(TH / 128, (TT * NB) / 128);   // (24, 256)
    gi_gemm_kernel<<<gg, 256>>>(x, w_ih, b_ih, gi);

    // Phase 2: sequential scan, one launch per timestep
    dim3 sg(HH / 16, 2);                  // (64, 2) = 128 blocks
    for (int tm = 0; tm < TT; tm++) {
        const float* hp = (tm == 0) ? hx : (out + (size_t)(tm - 1) * NB * HH);
        gru_step_kernel<<<sg, 256>>>(gi + (size_t)tm * NB * TH,
                                     mask + tm * NB,
                                     w_hh, b_hh,
                                     hp,
                                     out + (size_t)tm * NB * HH);
    }

    // h_final == out[T-1]
    cudaMemcpyAsync(out + (size_t)TT * NB * HH,
                    out + (size_t)(TT - 1) * NB * HH,
                    (size_t)NB * HH * sizeof(float),
                    cudaMemcpyDeviceToDevice, 0);
}